// round 15
// baseline (speedup 1.0000x reference)
#include <cuda_runtime.h>
#include <cuda_bf16.h>
#include <math.h>
#include <stdint.h>

#define N 4096
#define D 512
#define TAU_INV 5.0f
#define KSEL 820          // N - floor(0.8*(N-1)) = 4096 - 3276
#define NB 32             // 128-wide tiles per dim
#define NTILES 528
#define STG2 8            // D / 64
#define NBINS 512         // level-1 bins (u16-packed, 256 words x 2 halves)
#define NWORDS 256
#define SMEM_GEMM_BYTES 69632

// ---- device scratch (allocation-free) ----
__device__ __nv_bfloat16 g_hnh[(size_t)N * D];
__device__ float g_S[(size_t)N * N];
__device__ int   g_partner[N];
__device__ int   g_pneg[N];
__device__ int   g_pairidx[N];
__device__ float g_posexp[N];

__device__ __forceinline__ uint32_t smem_u32(const void* p) {
    uint32_t a;
    asm("{ .reg .u64 t; cvta.to.shared.u64 t, %1; cvt.u32.u64 %0, t; }" : "=r"(a) : "l"(p));
    return a;
}

// ---------------------------------------------------------------- fused prep (single block)
__global__ __launch_bounds__(1024) void k_prep(const int* __restrict__ pairs, int P,
                                               float* out) {
    int tid = threadIdx.x;
    if (tid == 0) out[0] = 0.0f;
    for (int i = tid; i < N; i += 1024) { g_partner[i] = -1; g_pairidx[i] = -1; }
    __syncthreads();
    for (int k = tid; k < P; k += 1024) {
        g_partner[pairs[2 * k]] = pairs[2 * k + 1];
        g_pairidx[pairs[2 * k]] = k;
    }
    __syncthreads();
    for (int i = tid; i < N; i += 1024) {
        int j = N - 1;
        while (j >= 0 && (j == i || g_partner[j] == i)) j--;
        g_pneg[i] = (j < 0) ? (N - 1) : j;
    }
}

// ---------------------------------------------------------------- fused hn (blocks 0..511) + pos (blocks 512..)
__global__ __launch_bounds__(256) void k_hnpos(const float* __restrict__ E,
                                               const int* __restrict__ pairs, int P) {
    int lane = threadIdx.x & 31;
    if (blockIdx.x < 512) {
        int w = blockIdx.x * 8 + (threadIdx.x >> 5);
        int pn = g_pneg[w];
        const float4* ei = (const float4*)(E + (size_t)w * D) + lane * 4;
        const float4* ep = (const float4*)(E + (size_t)pn * D) + lane * 4;
        float v[16];
        float ss = 0.0f;
#pragma unroll
        for (int q = 0; q < 4; q++) {
            float4 a = ei[q], b = ep[q];
            float m0 = 0.5f * a.x + 0.5f * b.x;
            float m1 = 0.5f * a.y + 0.5f * b.y;
            float m2 = 0.5f * a.z + 0.5f * b.z;
            float m3 = 0.5f * a.w + 0.5f * b.w;
            v[q * 4 + 0] = m0; v[q * 4 + 1] = m1; v[q * 4 + 2] = m2; v[q * 4 + 3] = m3;
            ss = fmaf(m0, m0, ss); ss = fmaf(m1, m1, ss);
            ss = fmaf(m2, m2, ss); ss = fmaf(m3, m3, ss);
        }
#pragma unroll
        for (int off = 16; off; off >>= 1) ss += __shfl_xor_sync(0xffffffffu, ss, off);
        float inv = 1.0f / fmaxf(sqrtf(ss), 1e-8f);
        __nv_bfloat16 h[16];
#pragma unroll
        for (int q = 0; q < 16; q++) h[q] = __float2bfloat16(v[q] * inv);
        uint4* dst = (uint4*)(g_hnh + (size_t)w * D + lane * 16);
        dst[0] = ((uint4*)h)[0];
        dst[1] = ((uint4*)h)[1];
    } else {
        int k = (blockIdx.x - 512) * 8 + (threadIdx.x >> 5);
        if (k >= P) return;
        int i = pairs[2 * k], j = pairs[2 * k + 1];
        int pi = g_partner[i], pj = g_partner[j];
        const float4* Ei  = (const float4*)(E + (size_t)i * D) + lane * 4;
        const float4* Ej  = (const float4*)(E + (size_t)j * D) + lane * 4;
        const float4* Epi = (const float4*)(E + (size_t)((pi >= 0) ? pi : 0) * D) + lane * 4;
        const float4* Epj = (const float4*)(E + (size_t)((pj >= 0) ? pj : 0) * D) + lane * 4;
        float daa = 0.f, dab = 0.f, dbb = 0.f;
#pragma unroll
        for (int q = 0; q < 4; q++) {
            float4 e1 = Ei[q], e2 = Ej[q], p1 = Epi[q], p2 = Epj[q];
            float a0 = (pi >= 0) ? (1.5f * e1.x - 0.5f * p1.x) : e1.x;
            float a1 = (pi >= 0) ? (1.5f * e1.y - 0.5f * p1.y) : e1.y;
            float a2 = (pi >= 0) ? (1.5f * e1.z - 0.5f * p1.z) : e1.z;
            float a3 = (pi >= 0) ? (1.5f * e1.w - 0.5f * p1.w) : e1.w;
            float b0 = (pj >= 0) ? (1.5f * e2.x - 0.5f * p2.x) : e2.x;
            float b1 = (pj >= 0) ? (1.5f * e2.y - 0.5f * p2.y) : e2.y;
            float b2 = (pj >= 0) ? (1.5f * e2.z - 0.5f * p2.z) : e2.z;
            float b3 = (pj >= 0) ? (1.5f * e2.w - 0.5f * p2.w) : e2.w;
            daa = fmaf(a0, a0, fmaf(a1, a1, fmaf(a2, a2, fmaf(a3, a3, daa))));
            dab = fmaf(a0, b0, fmaf(a1, b1, fmaf(a2, b2, fmaf(a3, b3, dab))));
            dbb = fmaf(b0, b0, fmaf(b1, b1, fmaf(b2, b2, fmaf(b3, b3, dbb))));
        }
#pragma unroll
        for (int off = 16; off; off >>= 1) {
            daa += __shfl_xor_sync(0xffffffffu, daa, off);
            dab += __shfl_xor_sync(0xffffffffu, dab, off);
            dbb += __shfl_xor_sync(0xffffffffu, dbb, off);
        }
        if (lane == 0) {
            float cosv = dab / (fmaxf(sqrtf(daa), 1e-8f) * fmaxf(sqrtf(dbb), 1e-8f));
            g_posexp[k] = expf(cosv * TAU_INV);
        }
    }
}

// ---------------------------------------------------------------- bf16 mma GEMM (R12/R14 2-stage, known good)
__device__ __forceinline__ void mma16(float* c, const uint32_t* a, const uint32_t* b) {
    asm volatile(
        "mma.sync.aligned.m16n8k16.row.col.f32.bf16.bf16.f32 "
        "{%0,%1,%2,%3}, {%4,%5,%6,%7}, {%8,%9}, {%0,%1,%2,%3};"
        : "+f"(c[0]), "+f"(c[1]), "+f"(c[2]), "+f"(c[3])
        : "r"(a[0]), "r"(a[1]), "r"(a[2]), "r"(a[3]), "r"(b[0]), "r"(b[1]));
}

__device__ __forceinline__ void ldsm_x4(uint32_t* r, uint32_t addr) {
    asm volatile("ldmatrix.sync.aligned.m8n8.x4.shared.b16 {%0,%1,%2,%3}, [%4];"
                 : "=r"(r[0]), "=r"(r[1]), "=r"(r[2]), "=r"(r[3]) : "r"(addr));
}

__device__ __forceinline__ void cp16(uint32_t dst, const void* src) {
    asm volatile("cp.async.cg.shared.global [%0], [%1], 16;" :: "r"(dst), "l"(src));
}

__global__ __launch_bounds__(512, 2) void k_gemm_bf16() {
    extern __shared__ char sm[];
    uint32_t sbase = smem_u32(sm);
    int tid = threadIdx.x;
    int lane = tid & 31, warp = tid >> 5;
    int wm = warp >> 2, wn = warp & 3;   // 4(M) x 4(N) warps, warp tile 32x32
    int g = lane >> 3, r8 = lane & 7;
    int ahi = g >> 1;

    int t = blockIdx.x, by = 0, rem = t;
    while (rem >= (NB - by)) { rem -= (NB - by); ++by; }
    int bx = by + rem;   // bx >= by

    const __nv_bfloat16* Abase = g_hnh + (size_t)by * 128 * D;
    const __nv_bfloat16* Bbase = g_hnh + (size_t)bx * 128 * D;

    float acc[2][4][4];
#pragma unroll
    for (int im = 0; im < 2; im++)
#pragma unroll
        for (int in = 0; in < 4; in++)
#pragma unroll
            for (int r = 0; r < 4; r++) acc[im][in][r] = 0.0f;

    auto async_load = [&](int s, int p) {
        uint32_t dstA = sbase + p * 32768;
        uint32_t dstB = dstA + 16384;
        int k0 = s * 64;
#pragma unroll
        for (int q = 0; q < 2; q++) {
            int id = tid + q * 512;          // 0..1023
            int row = id >> 3, c = id & 7;
            uint32_t off = (uint32_t)(row * 128 + ((c ^ (row & 7)) << 4));
            cp16(dstA + off, Abase + (size_t)row * D + k0 + c * 8);
            cp16(dstB + off, Bbase + (size_t)row * D + k0 + c * 8);
        }
        asm volatile("cp.async.commit_group;" ::: "memory");
    };

    auto compute = [&](int p) {
        uint32_t sA = sbase + p * 32768;
        uint32_t sB = sA + 16384;
        uint32_t arow[2]; int asw[2];
        uint32_t brow[2]; int bsw[2];
#pragma unroll
        for (int im = 0; im < 2; im++) {
            int rowA = wm * 32 + im * 16 + r8 + (g & 1) * 8;
            arow[im] = sA + rowA * 128;
            asw[im] = rowA & 7;
        }
#pragma unroll
        for (int inp = 0; inp < 2; inp++) {
            int rowB = wn * 32 + inp * 16 + r8 + (g >> 1) * 8;
            brow[inp] = sB + rowB * 128;
            bsw[inp] = rowB & 7;
        }
#pragma unroll
        for (int ks = 0; ks < 4; ks++) {
            uint32_t a[2][4], b2[2][4];
#pragma unroll
            for (int im = 0; im < 2; im++)
                ldsm_x4(a[im], arow[im] + (uint32_t)((((ks << 1) | ahi) ^ asw[im]) << 4));
#pragma unroll
            for (int inp = 0; inp < 2; inp++)
                ldsm_x4(b2[inp], brow[inp] + (uint32_t)((((ks << 1) | (g & 1)) ^ bsw[inp]) << 4));
#pragma unroll
            for (int im = 0; im < 2; im++)
#pragma unroll
                for (int in = 0; in < 4; in++)
                    mma16(acc[im][in], a[im], &b2[in >> 1][(in & 1) << 1]);
        }
    };

    async_load(0, 0);
    for (int s = 0; s < STG2; s++) {
        if (s + 1 < STG2) {
            async_load(s + 1, (s + 1) & 1);
            asm volatile("cp.async.wait_group 1;" ::: "memory");
        } else {
            asm volatile("cp.async.wait_group 0;" ::: "memory");
        }
        __syncthreads();
        compute(s & 1);
        __syncthreads();
    }

    // ---- epilogue via 128x132 fp32 smem tile ----
    float* stg = (float*)sm;
#pragma unroll
    for (int im = 0; im < 2; im++) {
        int row = wm * 32 + im * 16 + (lane >> 2);
#pragma unroll
        for (int in = 0; in < 4; in++) {
            int col = wn * 32 + in * 8 + (lane & 3) * 2;
            stg[row * 132 + col]           = acc[im][in][0];
            stg[row * 132 + col + 1]       = acc[im][in][1];
            stg[(row + 8) * 132 + col]     = acc[im][in][2];
            stg[(row + 8) * 132 + col + 1] = acc[im][in][3];
        }
    }
    __syncthreads();

    float* __restrict__ S = g_S;
    int r0 = by * 128, c0 = bx * 128;
#pragma unroll
    for (int q = 0; q < 8; q++) {
        int v = tid + q * 512;
        int row = v >> 5, c4 = (v & 31) << 2;
        float4 x = *(const float4*)(stg + row * 132 + c4);
        *(float4*)(S + (size_t)(r0 + row) * N + c0 + c4) = x;
    }
    if (bx != by) {
#pragma unroll
        for (int q = 0; q < 8; q++) {
            int v = tid + q * 512;
            int col = v >> 5, r4 = (v & 31) << 2;
            float4 x;
            x.x = stg[(r4 + 0) * 132 + col];
            x.y = stg[(r4 + 1) * 132 + col];
            x.z = stg[(r4 + 2) * 132 + col];
            x.w = stg[(r4 + 3) * 132 + col];
            *(float4*)(S + (size_t)(c0 + col) * N + r0 + r4) = x;
        }
    }
}

// ---------------------------------------------------------------- per-row top-K selection + sum + loss
// 512 level-1 bins, u16-packed per-warp hist: bin b -> word (b&255), half (b>>8).
// Adjacent-value bins land in different words -> hot-bin RED.S conflict halves.
__device__ __forceinline__ int bin_of(float v) {
    int b = (int)((v + 1.0f) * 256.0f);
    return b < 0 ? 0 : (b > (NBINS - 1) ? (NBINS - 1) : b);
}

__global__ __launch_bounds__(512, 4) void k_select(float* __restrict__ out, int P) {
    __shared__ float sval[N];                        // 16 KB
    __shared__ unsigned whist[16 * NWORDS];          // 16 KB (u16-packed per-warp hist)
    __shared__ int   hist[NBINS];                    // 2 KB
    __shared__ float list[2048];                     // 8 KB
    __shared__ float list2[256];                     // 1 KB (sub-bin candidates)
    __shared__ int   shist[256];                     // 1 KB
    __shared__ int   s_cnt, s_cnt2, s_b, s_kp, s_b2, s_kp2;
    __shared__ float s_thr;
    __shared__ float warpsum[16];

    int row = blockIdx.x;
    int tid = threadIdx.x;
    int lane = tid & 31, w = tid >> 5;
    int pi = g_partner[row];
    const float4* Sr4 = (const float4*)(g_S + (size_t)row * N);

    // front-load both global reads (MLP=2); latency overlaps init+barrier
    float4 va = Sr4[tid];
    float4 vb = Sr4[tid + 512];

    // whist init: 4096 u32 = 1024 uint4 -> 2 STS.128 per thread
    ((uint4*)whist)[tid] = make_uint4(0u, 0u, 0u, 0u);
    ((uint4*)whist)[tid + 512] = make_uint4(0u, 0u, 0u, 0u);
    if (tid < 256) shist[tid] = 0;
    if (tid == 0) { s_cnt = 0; s_cnt2 = 0; s_thr = -3.0f; s_b = 0; s_kp = 1; s_b2 = 0; s_kp2 = 1; }
    __syncthreads();

    // mask (rare-path range check), stash, per-warp packed atomic histogram
    {
        int jb = tid << 2;
        if ((unsigned)(row - jb) < 4u || (unsigned)(pi - jb) < 4u) {
            if (jb + 0 == row || jb + 0 == pi) va.x = -2.0f;
            if (jb + 1 == row || jb + 1 == pi) va.y = -2.0f;
            if (jb + 2 == row || jb + 2 == pi) va.z = -2.0f;
            if (jb + 3 == row || jb + 3 == pi) va.w = -2.0f;
        }
        int jb2 = (tid + 512) << 2;
        if ((unsigned)(row - jb2) < 4u || (unsigned)(pi - jb2) < 4u) {
            if (jb2 + 0 == row || jb2 + 0 == pi) vb.x = -2.0f;
            if (jb2 + 1 == row || jb2 + 1 == pi) vb.y = -2.0f;
            if (jb2 + 2 == row || jb2 + 2 == pi) vb.z = -2.0f;
            if (jb2 + 3 == row || jb2 + 3 == pi) vb.w = -2.0f;
        }
    }
    ((float4*)sval)[tid] = va;
    ((float4*)sval)[tid + 512] = vb;

    unsigned* wh = whist + w * NWORDS;
    {
        float vv[8] = {va.x, va.y, va.z, va.w, vb.x, vb.y, vb.z, vb.w};
#pragma unroll
        for (int c = 0; c < 8; c++) {
            int b = bin_of(vv[c]);
            atomicAdd(&wh[b & (NWORDS - 1)], 1u << ((b >> 8) << 4));   // RED.S, packed u16
        }
    }
    __syncthreads();

    // reduce per-warp packed histograms: word tid holds bins {tid, tid+256}
    if (tid < NWORDS) {
        unsigned c = 0;
#pragma unroll
        for (int ww = 0; ww < 16; ww++) c += whist[ww * NWORDS + tid];
        hist[tid] = (int)(c & 0xFFFFu);
        hist[tid + 256] = (int)(c >> 16);
    }
    __syncthreads();

    // locate bin containing KSEL-th largest (suffix scan, 16 bins/lane)
    if (tid < 32) {
        int c = 0;
#pragma unroll
        for (int q = 0; q < 16; q++) c += hist[tid * 16 + q];
        int suf = c;
#pragma unroll
        for (int off = 1; off < 32; off <<= 1) {
            int o = __shfl_down_sync(0xffffffffu, suf, off);
            if (tid + off < 32) suf += o;
        }
        int above = suf - c;
        if (above < KSEL && KSEL <= suf) {
            int remk = KSEL - above;
            int b = tid * 16;
            for (int q = 15; q >= 0; q--) {
                int h = hist[tid * 16 + q];
                if (remk <= h) { b = tid * 16 + q; break; }
                remk -= h;
            }
            s_b = b;
            s_kp = remk;
        }
    }
    __syncthreads();
    int bsel = s_b, kp = s_kp;
    float lo = (float)bsel * (1.0f / 256.0f) - 1.0f;

    // pass 2 (merged): exp-accumulate bins above boundary (provably >= thr),
    // gather boundary-bin candidates + sub-histogram
    float acc = 0.0f;
#pragma unroll
    for (int q = 0; q < 2; q++) {
        float4 v4 = ((const float4*)sval)[tid + q * 512];
        float vv[4] = {v4.x, v4.y, v4.z, v4.w};
#pragma unroll
        for (int c = 0; c < 4; c++) {
            float v = vv[c];
            int b = bin_of(v);
            if (b > bsel) {
                acc += __expf(v * TAU_INV);
            } else if (b == bsel) {
                int idx = atomicAdd(&s_cnt, 1);
                if (idx < 2048) {
                    list[idx] = v;
                    int sb = (int)((v - lo) * 65536.0f);
                    sb = sb < 0 ? 0 : (sb > 255 ? 255 : sb);
                    atomicAdd(&shist[sb], 1);
                }
            }
        }
    }
    __syncthreads();
    int cn = min(s_cnt, 2048);

    // locate sub-bin (8 sub-bins/lane)
    if (tid < 32) {
        int c = 0;
#pragma unroll
        for (int q = 0; q < 8; q++) c += shist[tid * 8 + q];
        int suf = c;
#pragma unroll
        for (int off = 1; off < 32; off <<= 1) {
            int o = __shfl_down_sync(0xffffffffu, suf, off);
            if (tid + off < 32) suf += o;
        }
        int above = suf - c;
        if (above < kp && kp <= suf) {
            int remk = kp - above;
            int b = tid * 8;
            for (int q = 7; q >= 0; q--) {
                int h = shist[tid * 8 + q];
                if (remk <= h) { b = tid * 8 + q; break; }
                remk -= h;
            }
            s_b2 = b;
            s_kp2 = remk;
        }
    }
    __syncthreads();
    int sb2 = s_b2, kp2 = s_kp2;

    // gather sub-bin candidates into tiny list2 (parallel)
    for (int t2 = tid; t2 < cn; t2 += 512) {
        float v = list[t2];
        int vs = (int)((v - lo) * 65536.0f);
        vs = vs < 0 ? 0 : (vs > 255 ? 255 : vs);
        if (vs == sb2) {
            int idx = atomicAdd(&s_cnt2, 1);
            if (idx < 256) list2[idx] = v;
        }
    }
    __syncthreads();
    int cn2 = min(s_cnt2, 256);

    // exact tie-aware rank within the tiny list (parallel, cn2 ~ 1-10)
    if (tid < cn2) {
        float v = list2[tid];
        int gt = 0, eq = 0;
        for (int m = 0; m < cn2; m++) {
            float wv = list2[m];
            gt += (wv > v);
            eq += (wv == v);
        }
        if (gt < kp2 && kp2 <= gt + eq) s_thr = v;
    }
    __syncthreads();
    float thr = s_thr;

    // boundary-bin survivors from list (bins > bsel already accumulated)
    for (int t2 = tid; t2 < cn; t2 += 512) {
        float v = list[t2];
        if (v >= thr) acc += __expf(v * TAU_INV);
    }
    for (int off = 16; off; off >>= 1) acc += __shfl_down_sync(0xffffffffu, acc, off);
    if (lane == 0) warpsum[w] = acc;
    __syncthreads();
    if (tid < 16) {
        float x = warpsum[tid];
        for (int off = 8; off; off >>= 1) x += __shfl_down_sync(0x0000ffffu, x, off);
        if (tid == 0) {
            int k = g_pairidx[row];
            if (k >= 0) {
                float pz = g_posexp[k];
                float loss = -logf(pz / (pz + x));
                atomicAdd(out, loss * (1.0f / (float)P));
            }
        }
    }
}

// ---------------------------------------------------------------- launch
extern "C" void kernel_launch(void* const* d_in, const int* in_sizes, int n_in,
                              void* d_out, int out_size) {
    const float* E = (const float*)d_in[0];
    const int* pairs = (const int*)d_in[1];
    float* out = (float*)d_out;
    int P = in_sizes[1] / 2;

    static int smem_set = 0;
    if (!smem_set) {
        cudaFuncSetAttribute(k_gemm_bf16, cudaFuncAttributeMaxDynamicSharedMemorySize,
                             SMEM_GEMM_BYTES);
        smem_set = 1;
    }

    // 4 launches; select is the 4th (ncu capture slot)
    k_prep<<<1, 1024>>>(pairs, P, out);
    k_hnpos<<<512 + (P + 7) / 8, 256>>>(E, pairs, P);
    k_gemm_bf16<<<NTILES, 512, SMEM_GEMM_BYTES>>>();
    k_select<<<N, 512>>>(out, P);
}

// round 16
// speedup vs baseline: 1.0458x; 1.0458x over previous
#include <cuda_runtime.h>
#include <cuda_bf16.h>
#include <cuda_fp16.h>
#include <math.h>
#include <stdint.h>

#define N 4096
#define D 512
#define TAU_INV 5.0f
#define KSEL 820          // N - floor(0.8*(N-1)) = 4096 - 3276
#define NB 32             // 128-wide tiles per dim
#define NTILES 528
#define STG2 8            // D / 64
#define NBINS 256
#define SMEM_GEMM_BYTES 69632

// ---- device scratch (allocation-free) ----
__device__ __nv_bfloat16 g_hnh[(size_t)N * D];
__device__ __half g_Sh[(size_t)N * N];           // fp16 sim matrix (32 MB)
__device__ int   g_partner[N];
__device__ int   g_pneg[N];
__device__ int   g_pairidx[N];
__device__ float g_posexp[N];

__device__ __forceinline__ uint32_t smem_u32(const void* p) {
    uint32_t a;
    asm("{ .reg .u64 t; cvta.to.shared.u64 t, %1; cvt.u32.u64 %0, t; }" : "=r"(a) : "l"(p));
    return a;
}

__device__ __forceinline__ unsigned pack_h2(float a, float b) {
    __half2 h = __floats2half2_rn(a, b);
    return *(unsigned*)&h;
}

// ---------------------------------------------------------------- fused prep (single block)
__global__ __launch_bounds__(1024) void k_prep(const int* __restrict__ pairs, int P,
                                               float* out) {
    int tid = threadIdx.x;
    if (tid == 0) out[0] = 0.0f;
    for (int i = tid; i < N; i += 1024) { g_partner[i] = -1; g_pairidx[i] = -1; }
    __syncthreads();
    for (int k = tid; k < P; k += 1024) {
        g_partner[pairs[2 * k]] = pairs[2 * k + 1];
        g_pairidx[pairs[2 * k]] = k;
    }
    __syncthreads();
    for (int i = tid; i < N; i += 1024) {
        int j = N - 1;
        while (j >= 0 && (j == i || g_partner[j] == i)) j--;
        g_pneg[i] = (j < 0) ? (N - 1) : j;
    }
}

// ---------------------------------------------------------------- fused hn (blocks 0..511) + pos (blocks 512..)
__global__ __launch_bounds__(256) void k_hnpos(const float* __restrict__ E,
                                               const int* __restrict__ pairs, int P) {
    int lane = threadIdx.x & 31;
    if (blockIdx.x < 512) {
        int w = blockIdx.x * 8 + (threadIdx.x >> 5);
        int pn = g_pneg[w];
        const float4* ei = (const float4*)(E + (size_t)w * D) + lane * 4;
        const float4* ep = (const float4*)(E + (size_t)pn * D) + lane * 4;
        float v[16];
        float ss = 0.0f;
#pragma unroll
        for (int q = 0; q < 4; q++) {
            float4 a = ei[q], b = ep[q];
            float m0 = 0.5f * a.x + 0.5f * b.x;
            float m1 = 0.5f * a.y + 0.5f * b.y;
            float m2 = 0.5f * a.z + 0.5f * b.z;
            float m3 = 0.5f * a.w + 0.5f * b.w;
            v[q * 4 + 0] = m0; v[q * 4 + 1] = m1; v[q * 4 + 2] = m2; v[q * 4 + 3] = m3;
            ss = fmaf(m0, m0, ss); ss = fmaf(m1, m1, ss);
            ss = fmaf(m2, m2, ss); ss = fmaf(m3, m3, ss);
        }
#pragma unroll
        for (int off = 16; off; off >>= 1) ss += __shfl_xor_sync(0xffffffffu, ss, off);
        float inv = 1.0f / fmaxf(sqrtf(ss), 1e-8f);
        __nv_bfloat16 h[16];
#pragma unroll
        for (int q = 0; q < 16; q++) h[q] = __float2bfloat16(v[q] * inv);
        uint4* dst = (uint4*)(g_hnh + (size_t)w * D + lane * 16);
        dst[0] = ((uint4*)h)[0];
        dst[1] = ((uint4*)h)[1];
    } else {
        int k = (blockIdx.x - 512) * 8 + (threadIdx.x >> 5);
        if (k >= P) return;
        int i = pairs[2 * k], j = pairs[2 * k + 1];
        int pi = g_partner[i], pj = g_partner[j];
        const float4* Ei  = (const float4*)(E + (size_t)i * D) + lane * 4;
        const float4* Ej  = (const float4*)(E + (size_t)j * D) + lane * 4;
        const float4* Epi = (const float4*)(E + (size_t)((pi >= 0) ? pi : 0) * D) + lane * 4;
        const float4* Epj = (const float4*)(E + (size_t)((pj >= 0) ? pj : 0) * D) + lane * 4;
        float daa = 0.f, dab = 0.f, dbb = 0.f;
#pragma unroll
        for (int q = 0; q < 4; q++) {
            float4 e1 = Ei[q], e2 = Ej[q], p1 = Epi[q], p2 = Epj[q];
            float a0 = (pi >= 0) ? (1.5f * e1.x - 0.5f * p1.x) : e1.x;
            float a1 = (pi >= 0) ? (1.5f * e1.y - 0.5f * p1.y) : e1.y;
            float a2 = (pi >= 0) ? (1.5f * e1.z - 0.5f * p1.z) : e1.z;
            float a3 = (pi >= 0) ? (1.5f * e1.w - 0.5f * p1.w) : e1.w;
            float b0 = (pj >= 0) ? (1.5f * e2.x - 0.5f * p2.x) : e2.x;
            float b1 = (pj >= 0) ? (1.5f * e2.y - 0.5f * p2.y) : e2.y;
            float b2 = (pj >= 0) ? (1.5f * e2.z - 0.5f * p2.z) : e2.z;
            float b3 = (pj >= 0) ? (1.5f * e2.w - 0.5f * p2.w) : e2.w;
            daa = fmaf(a0, a0, fmaf(a1, a1, fmaf(a2, a2, fmaf(a3, a3, daa))));
            dab = fmaf(a0, b0, fmaf(a1, b1, fmaf(a2, b2, fmaf(a3, b3, dab))));
            dbb = fmaf(b0, b0, fmaf(b1, b1, fmaf(b2, b2, fmaf(b3, b3, dbb))));
        }
#pragma unroll
        for (int off = 16; off; off >>= 1) {
            daa += __shfl_xor_sync(0xffffffffu, daa, off);
            dab += __shfl_xor_sync(0xffffffffu, dab, off);
            dbb += __shfl_xor_sync(0xffffffffu, dbb, off);
        }
        if (lane == 0) {
            float cosv = dab / (fmaxf(sqrtf(daa), 1e-8f) * fmaxf(sqrtf(dbb), 1e-8f));
            g_posexp[k] = expf(cosv * TAU_INV);
        }
    }
}

// ---------------------------------------------------------------- bf16 mma GEMM (2-stage, fp16 output)
__device__ __forceinline__ void mma16(float* c, const uint32_t* a, const uint32_t* b) {
    asm volatile(
        "mma.sync.aligned.m16n8k16.row.col.f32.bf16.bf16.f32 "
        "{%0,%1,%2,%3}, {%4,%5,%6,%7}, {%8,%9}, {%0,%1,%2,%3};"
        : "+f"(c[0]), "+f"(c[1]), "+f"(c[2]), "+f"(c[3])
        : "r"(a[0]), "r"(a[1]), "r"(a[2]), "r"(a[3]), "r"(b[0]), "r"(b[1]));
}

__device__ __forceinline__ void ldsm_x4(uint32_t* r, uint32_t addr) {
    asm volatile("ldmatrix.sync.aligned.m8n8.x4.shared.b16 {%0,%1,%2,%3}, [%4];"
                 : "=r"(r[0]), "=r"(r[1]), "=r"(r[2]), "=r"(r[3]) : "r"(addr));
}

__device__ __forceinline__ void cp16(uint32_t dst, const void* src) {
    asm volatile("cp.async.cg.shared.global [%0], [%1], 16;" :: "r"(dst), "l"(src));
}

__global__ __launch_bounds__(512, 2) void k_gemm_bf16() {
    extern __shared__ char sm[];
    uint32_t sbase = smem_u32(sm);
    int tid = threadIdx.x;
    int lane = tid & 31, warp = tid >> 5;
    int wm = warp >> 2, wn = warp & 3;   // 4(M) x 4(N) warps, warp tile 32x32
    int g = lane >> 3, r8 = lane & 7;
    int ahi = g >> 1;

    int t = blockIdx.x, by = 0, rem = t;
    while (rem >= (NB - by)) { rem -= (NB - by); ++by; }
    int bx = by + rem;   // bx >= by

    const __nv_bfloat16* Abase = g_hnh + (size_t)by * 128 * D;
    const __nv_bfloat16* Bbase = g_hnh + (size_t)bx * 128 * D;

    float acc[2][4][4];
#pragma unroll
    for (int im = 0; im < 2; im++)
#pragma unroll
        for (int in = 0; in < 4; in++)
#pragma unroll
            for (int r = 0; r < 4; r++) acc[im][in][r] = 0.0f;

    auto async_load = [&](int s, int p) {
        uint32_t dstA = sbase + p * 32768;
        uint32_t dstB = dstA + 16384;
        int k0 = s * 64;
#pragma unroll
        for (int q = 0; q < 2; q++) {
            int id = tid + q * 512;          // 0..1023
            int row = id >> 3, c = id & 7;
            uint32_t off = (uint32_t)(row * 128 + ((c ^ (row & 7)) << 4));
            cp16(dstA + off, Abase + (size_t)row * D + k0 + c * 8);
            cp16(dstB + off, Bbase + (size_t)row * D + k0 + c * 8);
        }
        asm volatile("cp.async.commit_group;" ::: "memory");
    };

    auto compute = [&](int p) {
        uint32_t sA = sbase + p * 32768;
        uint32_t sB = sA + 16384;
        uint32_t arow[2]; int asw[2];
        uint32_t brow[2]; int bsw[2];
#pragma unroll
        for (int im = 0; im < 2; im++) {
            int rowA = wm * 32 + im * 16 + r8 + (g & 1) * 8;
            arow[im] = sA + rowA * 128;
            asw[im] = rowA & 7;
        }
#pragma unroll
        for (int inp = 0; inp < 2; inp++) {
            int rowB = wn * 32 + inp * 16 + r8 + (g >> 1) * 8;
            brow[inp] = sB + rowB * 128;
            bsw[inp] = rowB & 7;
        }
#pragma unroll
        for (int ks = 0; ks < 4; ks++) {
            uint32_t a[2][4], b2[2][4];
#pragma unroll
            for (int im = 0; im < 2; im++)
                ldsm_x4(a[im], arow[im] + (uint32_t)((((ks << 1) | ahi) ^ asw[im]) << 4));
#pragma unroll
            for (int inp = 0; inp < 2; inp++)
                ldsm_x4(b2[inp], brow[inp] + (uint32_t)((((ks << 1) | (g & 1)) ^ bsw[inp]) << 4));
#pragma unroll
            for (int im = 0; im < 2; im++)
#pragma unroll
                for (int in = 0; in < 4; in++)
                    mma16(acc[im][in], a[im], &b2[in >> 1][(in & 1) << 1]);
        }
    };

    async_load(0, 0);
    for (int s = 0; s < STG2; s++) {
        if (s + 1 < STG2) {
            async_load(s + 1, (s + 1) & 1);
            asm volatile("cp.async.wait_group 1;" ::: "memory");
        } else {
            asm volatile("cp.async.wait_group 0;" ::: "memory");
        }
        __syncthreads();
        compute(s & 1);
        __syncthreads();
    }

    // ---- epilogue: fp32 smem staging tile -> fp16 global (direct + mirror) ----
    float* stg = (float*)sm;
#pragma unroll
    for (int im = 0; im < 2; im++) {
        int row = wm * 32 + im * 16 + (lane >> 2);
#pragma unroll
        for (int in = 0; in < 4; in++) {
            int col = wn * 32 + in * 8 + (lane & 3) * 2;
            stg[row * 132 + col]           = acc[im][in][0];
            stg[row * 132 + col + 1]       = acc[im][in][1];
            stg[(row + 8) * 132 + col]     = acc[im][in][2];
            stg[(row + 8) * 132 + col + 1] = acc[im][in][3];
        }
    }
    __syncthreads();

    __half* __restrict__ S = g_Sh;
    int r0 = by * 128, c0 = bx * 128;
#pragma unroll
    for (int q = 0; q < 4; q++) {
        int v = tid + q * 512;               // 0..2047
        int row = v >> 4, c8 = (v & 15) << 3;
        float4 x0 = *(const float4*)(stg + row * 132 + c8);
        float4 x1 = *(const float4*)(stg + row * 132 + c8 + 4);
        uint4 h;
        h.x = pack_h2(x0.x, x0.y); h.y = pack_h2(x0.z, x0.w);
        h.z = pack_h2(x1.x, x1.y); h.w = pack_h2(x1.z, x1.w);
        *(uint4*)(S + (size_t)(r0 + row) * N + c0 + c8) = h;
    }
    if (bx != by) {
#pragma unroll
        for (int q = 0; q < 4; q++) {
            int v = tid + q * 512;
            int col = v >> 4, r8 = (v & 15) << 3;
            float x[8];
#pragma unroll
            for (int i = 0; i < 8; i++) x[i] = stg[(r8 + i) * 132 + col];
            uint4 h;
            h.x = pack_h2(x[0], x[1]); h.y = pack_h2(x[2], x[3]);
            h.z = pack_h2(x[4], x[5]); h.w = pack_h2(x[6], x[7]);
            *(uint4*)(S + (size_t)(c0 + col) * N + r0 + r8) = h;
        }
    }
}

// ---------------------------------------------------------------- per-row top-K selection + sum + loss
// fp16 row: ONE LDG.128 per thread (8 halves). R14-proven structure otherwise.
__device__ __forceinline__ int bin_of(float v) {
    int b = (int)((v + 1.0f) * 128.0f);
    return b < 0 ? 0 : (b > (NBINS - 1) ? (NBINS - 1) : b);
}

__global__ __launch_bounds__(512, 4) void k_select(float* __restrict__ out, int P) {
    __shared__ float sval[N];                        // 16 KB
    __shared__ unsigned whist[16 * NBINS];           // 16 KB (u32 per-warp hist)
    __shared__ int   hist[NBINS];                    // 1 KB
    __shared__ float list[2048];                     // 8 KB
    __shared__ float list2[256];                     // 1 KB
    __shared__ int   shist[256];                     // 1 KB
    __shared__ int   s_cnt, s_cnt2, s_b, s_kp, s_b2, s_kp2;
    __shared__ float s_thr;
    __shared__ float warpsum[16];

    int row = blockIdx.x;
    int tid = threadIdx.x;
    int lane = tid & 31, w = tid >> 5;
    int pi = g_partner[row];

    // front-load the single global read: 16 B = this thread's whole 8-element slice
    uint4 hv = ((const uint4*)(g_Sh + (size_t)row * N))[tid];

    // whist init: 4096 u32 = 1024 uint4 -> 2 STS.128 per thread
    ((uint4*)whist)[tid] = make_uint4(0u, 0u, 0u, 0u);
    ((uint4*)whist)[tid + 512] = make_uint4(0u, 0u, 0u, 0u);
    if (tid < 256) shist[tid] = 0;
    if (tid == 0) { s_cnt = 0; s_cnt2 = 0; s_thr = -3.0f; s_b = 0; s_kp = 1; s_b2 = 0; s_kp2 = 1; }
    __syncthreads();

    // convert, mask (rare-path), stash, per-warp atomic histogram
    float f[8];
    {
        __half2* hp = (__half2*)&hv;
        float2 f0 = __half22float2(hp[0]);
        float2 f1 = __half22float2(hp[1]);
        float2 f2 = __half22float2(hp[2]);
        float2 f3 = __half22float2(hp[3]);
        f[0] = f0.x; f[1] = f0.y; f[2] = f1.x; f[3] = f1.y;
        f[4] = f2.x; f[5] = f2.y; f[6] = f3.x; f[7] = f3.y;
        int jb = tid << 3;
        if ((unsigned)(row - jb) < 8u || (unsigned)(pi - jb) < 8u) {
#pragma unroll
            for (int c = 0; c < 8; c++)
                if (jb + c == row || jb + c == pi) f[c] = -2.0f;
        }
    }
    ((float4*)sval)[tid * 2]     = make_float4(f[0], f[1], f[2], f[3]);
    ((float4*)sval)[tid * 2 + 1] = make_float4(f[4], f[5], f[6], f[7]);

    unsigned* wh = whist + w * NBINS;
#pragma unroll
    for (int c = 0; c < 8; c++)
        atomicAdd(&wh[bin_of(f[c])], 1u);   // RED.S fire-and-forget
    __syncthreads();

    // reduce per-warp histograms
    if (tid < NBINS) {
        unsigned c = 0;
#pragma unroll
        for (int ww = 0; ww < 16; ww++) c += whist[ww * NBINS + tid];
        hist[tid] = (int)c;
    }
    __syncthreads();

    // locate bin containing KSEL-th largest (suffix scan, 8 bins/lane)
    if (tid < 32) {
        int c = 0;
#pragma unroll
        for (int q = 0; q < 8; q++) c += hist[tid * 8 + q];
        int suf = c;
#pragma unroll
        for (int off = 1; off < 32; off <<= 1) {
            int o = __shfl_down_sync(0xffffffffu, suf, off);
            if (tid + off < 32) suf += o;
        }
        int above = suf - c;
        if (above < KSEL && KSEL <= suf) {
            int remk = KSEL - above;
            int b = tid * 8;
            for (int q = 7; q >= 0; q--) {
                int h = hist[tid * 8 + q];
                if (remk <= h) { b = tid * 8 + q; break; }
                remk -= h;
            }
            s_b = b;
            s_kp = remk;
        }
    }
    __syncthreads();
    int bsel = s_b, kp = s_kp;
    float lo = (float)bsel * (1.0f / 128.0f) - 1.0f;

    // pass 2 (merged): exp-accumulate bins above boundary; gather boundary bin + sub-hist
    float acc = 0.0f;
#pragma unroll
    for (int q = 0; q < 2; q++) {
        float4 v4 = ((const float4*)sval)[tid + q * 512];
        float vv[4] = {v4.x, v4.y, v4.z, v4.w};
#pragma unroll
        for (int c = 0; c < 4; c++) {
            float v = vv[c];
            int b = bin_of(v);
            if (b > bsel) {
                acc += __expf(v * TAU_INV);
            } else if (b == bsel) {
                int idx = atomicAdd(&s_cnt, 1);
                if (idx < 2048) {
                    list[idx] = v;
                    int sb = (int)((v - lo) * 32768.0f);
                    sb = sb < 0 ? 0 : (sb > 255 ? 255 : sb);
                    atomicAdd(&shist[sb], 1);
                }
            }
        }
    }
    __syncthreads();
    int cn = min(s_cnt, 2048);

    // locate sub-bin (8 sub-bins/lane)
    if (tid < 32) {
        int c = 0;
#pragma unroll
        for (int q = 0; q < 8; q++) c += shist[tid * 8 + q];
        int suf = c;
#pragma unroll
        for (int off = 1; off < 32; off <<= 1) {
            int o = __shfl_down_sync(0xffffffffu, suf, off);
            if (tid + off < 32) suf += o;
        }
        int above = suf - c;
        if (above < kp && kp <= suf) {
            int remk = kp - above;
            int b = tid * 8;
            for (int q = 7; q >= 0; q--) {
                int h = shist[tid * 8 + q];
                if (remk <= h) { b = tid * 8 + q; break; }
                remk -= h;
            }
            s_b2 = b;
            s_kp2 = remk;
        }
    }
    __syncthreads();
    int sb2 = s_b2, kp2 = s_kp2;

    // gather sub-bin candidates into tiny list2 (parallel)
    for (int t2 = tid; t2 < cn; t2 += 512) {
        float v = list[t2];
        int vs = (int)((v - lo) * 32768.0f);
        vs = vs < 0 ? 0 : (vs > 255 ? 255 : vs);
        if (vs == sb2) {
            int idx = atomicAdd(&s_cnt2, 1);
            if (idx < 256) list2[idx] = v;
        }
    }
    __syncthreads();
    int cn2 = min(s_cnt2, 256);

    // exact tie-aware rank within the tiny list (parallel)
    if (tid < cn2) {
        float v = list2[tid];
        int gt = 0, eq = 0;
        for (int m = 0; m < cn2; m++) {
            float wv = list2[m];
            gt += (wv > v);
            eq += (wv == v);
        }
        if (gt < kp2 && kp2 <= gt + eq) s_thr = v;
    }
    __syncthreads();
    float thr = s_thr;

    // boundary-bin survivors from list (bins > bsel already accumulated)
    for (int t2 = tid; t2 < cn; t2 += 512) {
        float v = list[t2];
        if (v >= thr) acc += __expf(v * TAU_INV);
    }
    for (int off = 16; off; off >>= 1) acc += __shfl_down_sync(0xffffffffu, acc, off);
    if (lane == 0) warpsum[w] = acc;
    __syncthreads();
    if (tid < 16) {
        float x = warpsum[tid];
        for (int off = 8; off; off >>= 1) x += __shfl_down_sync(0x0000ffffu, x, off);
        if (tid == 0) {
            int k = g_pairidx[row];
            if (k >= 0) {
                float pz = g_posexp[k];
                float loss = -logf(pz / (pz + x));
                atomicAdd(out, loss * (1.0f / (float)P));
            }
        }
    }
}

// ---------------------------------------------------------------- launch
extern "C" void kernel_launch(void* const* d_in, const int* in_sizes, int n_in,
                              void* d_out, int out_size) {
    const float* E = (const float*)d_in[0];
    const int* pairs = (const int*)d_in[1];
    float* out = (float*)d_out;
    int P = in_sizes[1] / 2;

    static int smem_set = 0;
    if (!smem_set) {
        cudaFuncSetAttribute(k_gemm_bf16, cudaFuncAttributeMaxDynamicSharedMemorySize,
                             SMEM_GEMM_BYTES);
        smem_set = 1;
    }

    // 4 launches; select is the 4th (ncu capture slot)
    k_prep<<<1, 1024>>>(pairs, P, out);
    k_hnpos<<<512 + (P + 7) / 8, 256>>>(E, pairs, P);
    k_gemm_bf16<<<NTILES, 512, SMEM_GEMM_BYTES>>>();
    k_select<<<N, 512>>>(out, P);
}